// round 7
// baseline (speedup 1.0000x reference)
#include <cuda_runtime.h>

#define NN 4096

typedef unsigned long long ull;

__device__ __forceinline__ ull pack2(float lo, float hi) {
    ull r; asm("mov.b64 %0, {%1, %2};" : "=l"(r) : "f"(lo), "f"(hi)); return r;
}
__device__ __forceinline__ void unpack2(ull v, float &lo, float &hi) {
    asm("mov.b64 {%0, %1}, %2;" : "=f"(lo), "=f"(hi) : "l"(v));
}
__device__ __forceinline__ void ffma2(ull &d, ull a, ull b) {
    asm("fma.rn.f32x2 %0, %1, %2, %0;" : "+l"(d) : "l"(a), "l"(b));
}
__device__ __forceinline__ unsigned smem_u32(const void* p) {
    unsigned a;
    asm("{ .reg .u64 t; cvta.to.shared.u64 t, %1; cvt.u32.u64 %0, t; }" : "=r"(a) : "l"(p));
    return a;
}
__device__ __forceinline__ unsigned bf2(float hi, float lo) {
    unsigned r; asm("cvt.rn.bf16x2.f32 %0, %1, %2;" : "=r"(r) : "f"(hi), "f"(lo)); return r;
}
__device__ __forceinline__ void ldm4(unsigned &a0, unsigned &a1, unsigned &a2, unsigned &a3,
                                     unsigned addr) {
    asm volatile("ldmatrix.sync.aligned.m8n8.x4.shared.b16 {%0,%1,%2,%3}, [%4];"
                 : "=r"(a0), "=r"(a1), "=r"(a2), "=r"(a3) : "r"(addr));
}
__device__ __forceinline__ void mma16816(float* d, unsigned a0, unsigned a1, unsigned a2,
                                         unsigned a3, unsigned b0, unsigned b1) {
    asm volatile(
        "mma.sync.aligned.m16n8k16.row.col.f32.bf16.bf16.f32 "
        "{%0,%1,%2,%3}, {%4,%5,%6,%7}, {%8,%9}, {%0,%1,%2,%3};"
        : "+f"(d[0]), "+f"(d[1]), "+f"(d[2]), "+f"(d[3])
        : "r"(a0), "r"(a1), "r"(a2), "r"(a3), "r"(b0), "r"(b1));
}

// ---------------- scratch ----------------
__device__ float g_feats[8 * 80 * NN];      // [b][0:8]=featB [8:16]=featC [16:80]=featD
__device__ float g_x1[8 * 64 * NN];         // after PAM
__device__ float g_x2[8 * 64 * NN];         // after CAM
__device__ float g_gramP[8 * 16 * 64 * 64]; // partial grams
__device__ float g_attG[8 * 64 * 64];       // CAM attention
__device__ float g_conv[8 * 128 * NN];      // conv3x3 output
__device__ float g_mean[128];
__device__ float g_rstd[128];

// ---------------- K1: fused 1x1 convs -> featB/featC/featD ----------------
__global__ void __launch_bounds__(256) k1_conv1x1(
    const float* __restrict__ x,
    const float* __restrict__ wb, const float* __restrict__ bbv,
    const float* __restrict__ wc, const float* __restrict__ bcv,
    const float* __restrict__ wd, const float* __restrict__ bdv)
{
    __shared__ __align__(16) float ws[80 * 64];
    __shared__ float bs[80];
    const int t = threadIdx.x;
    const int b = blockIdx.y;
    const int n = blockIdx.x * 256 + t;

    for (int idx = t; idx < 80 * 64; idx += 256) {
        int row = idx >> 6;
        float v;
        if (row < 8)       v = wb[idx];
        else if (row < 16) v = wc[idx - 512];
        else               v = wd[idx - 1024];
        ws[idx] = v;
    }
    if (t < 80) bs[t] = (t < 8) ? bbv[t] : (t < 16 ? bcv[t - 8] : bdv[t - 16]);
    __syncthreads();

    float xr[64];
    const float* xb = x + b * 64 * NN + n;
    #pragma unroll
    for (int c = 0; c < 64; c++) xr[c] = xb[c * NN];

    float* dst = g_feats + b * 80 * NN + n;
    for (int o = 0; o < 80; o++) {
        float acc = bs[o];
        const float4* w4 = (const float4*)(ws + o * 64);
        #pragma unroll
        for (int c4 = 0; c4 < 16; c4++) {
            float4 w = w4[c4];
            acc += w.x * xr[4 * c4] + w.y * xr[4 * c4 + 1]
                 + w.z * xr[4 * c4 + 2] + w.w * xr[4 * c4 + 3];
        }
        dst[o * NN] = acc;
    }
}

// ---------------- K2: PAM flash attention, AV on mma.sync bf16 -------------
// 128 queries per block, keys in tiles of 64.
// S phase: fp32 QK + expf -> P bf16 [128q][72 stride] smem; V bf16 [64c][72].
// AV: mma.sync.m16n8k16 row.col, A=P tile (16qx16m), B=V (col-major [c][m]).
// Warp w owns q rows w*16..w*16+15, all 64 c. Epilogue staged via smem O.
// smem layout (bytes): Lq @0 (512), union { P @512 (18432), V @18944 (9216),
// Qs @28160 (4096 f32 [q][8]) } vs { O @512 (128x65 f32 = 33280) }. total 33792.
__global__ void __launch_bounds__(256) k2_flash_mma(const float* __restrict__ x,
                                                    const float* __restrict__ alpha)
{
    __shared__ __align__(16) char sm[33792];
    const unsigned sb = smem_u32(sm);
    const unsigned Po = sb + 512;
    const unsigned Vo = sb + 18944;
    float* Qs = (float*)(sm + 28160);
    float* Lq = (float*)sm;
    float* Osm = (float*)(sm + 512);

    const int t = threadIdx.x;
    const int wid = t >> 5, lid = t & 31;
    const int b = blockIdx.y;
    const int q0 = blockIdx.x * 128;
    const float* fB = g_feats + b * 80 * NN;
    const float* fC = fB + 8 * NN;
    const float* fD = fB + 16 * NN;

    // Q transposed into smem: Qs[q][k], k=0..7
    {
        int q = t & 127, kh = (t >> 7) * 4;
        #pragma unroll
        for (int k = 0; k < 4; k++)
            Qs[q * 8 + kh + k] = fB[(kh + k) * NN + q0 + q];
    }

    const int q0w = wid * 16;
    const int vc = t >> 2, vms = (t & 3) * 16;   // V copy mapping

    float lacc[16];
    #pragma unroll
    for (int i = 0; i < 16; i++) lacc[i] = 0.f;
    float acc[8][4];
    #pragma unroll
    for (int i = 0; i < 8; i++)
        #pragma unroll
        for (int j = 0; j < 4; j++) acc[i][j] = 0.f;

    for (int kt = 0; kt < 64; kt++) {
        const int m0 = kt * 64;
        __syncthreads();   // AV of previous tile done reading P/V

        // ---- V tile: [c][m] bf16, row stride 144B ----
        {
            const float* src = fD + vc * NN + m0 + vms;
            unsigned vaddr = Vo + vc * 144 + vms * 2;
            #pragma unroll
            for (int j = 0; j < 2; j++) {
                float4 f0 = *(const float4*)(src + 8 * j);
                float4 f1 = *(const float4*)(src + 8 * j + 4);
                unsigned p0 = bf2(f0.y, f0.x), p1 = bf2(f0.w, f0.z);
                unsigned p2 = bf2(f1.y, f1.x), p3 = bf2(f1.w, f1.z);
                asm volatile("st.shared.v4.b32 [%0], {%1,%2,%3,%4};"
                             :: "r"(vaddr + 16 * j), "r"(p0), "r"(p1), "r"(p2), "r"(p3));
            }
        }

        // ---- S phase: warp w covers q=q0w..+15, lane covers m=2*lid,2*lid+1 ----
        float2 kr[8];
        #pragma unroll
        for (int k = 0; k < 8; k++)
            kr[k] = *(const float2*)(fC + k * NN + m0 + 2 * lid);
        #pragma unroll
        for (int i = 0; i < 16; i++) {
            const float4 qa = *(const float4*)(Qs + (q0w + i) * 8);
            const float4 qb = *(const float4*)(Qs + (q0w + i) * 8 + 4);
            float s0 = qa.x * kr[0].x + qa.y * kr[1].x + qa.z * kr[2].x + qa.w * kr[3].x
                     + qb.x * kr[4].x + qb.y * kr[5].x + qb.z * kr[6].x + qb.w * kr[7].x;
            float s1 = qa.x * kr[0].y + qa.y * kr[1].y + qa.z * kr[2].y + qa.w * kr[3].y
                     + qb.x * kr[4].y + qb.y * kr[5].y + qb.z * kr[6].y + qb.w * kr[7].y;
            float p0 = __expf(s0), p1 = __expf(s1);
            lacc[i] += p0 + p1;
            unsigned pr = bf2(p1, p0);
            asm volatile("st.shared.b32 [%0], %1;"
                         :: "r"(Po + (q0w + i) * 144 + lid * 4), "r"(pr));
        }
        __syncthreads();

        // ---- AV: 4 k-chunks x 8 n-tiles of mma.sync ----
        #pragma unroll
        for (int kc = 0; kc < 4; kc++) {
            unsigned a0, a1, a2, a3;
            unsigned aaddr = Po + (q0w + (lid & 15)) * 144 + kc * 32 + (lid >> 4) * 16;
            ldm4(a0, a1, a2, a3, aaddr);
            #pragma unroll
            for (int nt = 0; nt < 4; nt++) {
                unsigned r0, r1, r2, r3;
                unsigned baddr = Vo + (nt * 16 + (lid & 7) + ((lid >> 4) & 1) * 8) * 144
                               + (kc * 16 + ((lid >> 3) & 1) * 8) * 2;
                ldm4(r0, r1, r2, r3, baddr);
                mma16816(acc[2 * nt],     a0, a1, a2, a3, r0, r1);
                mma16816(acc[2 * nt + 1], a0, a1, a2, a3, r2, r3);
            }
        }
    }

    // ---- softmax denominators ----
    #pragma unroll
    for (int i = 0; i < 16; i++) {
        float v = lacc[i];
        #pragma unroll
        for (int o = 16; o; o >>= 1) v += __shfl_xor_sync(0xffffffffu, v, o);
        if (lid == 0) Lq[q0w + i] = v;
    }
    __syncthreads();   // all AV done (P/V dead), Lq visible

    // ---- stage O to smem [q][65] fp32 ----
    #pragma unroll
    for (int nt8 = 0; nt8 < 8; nt8++) {
        int cb = nt8 * 8 + 2 * (lid & 3);
        int r = q0w + (lid >> 2);
        Osm[r * 65 + cb]           = acc[nt8][0];
        Osm[r * 65 + cb + 1]       = acc[nt8][1];
        Osm[(r + 8) * 65 + cb]     = acc[nt8][2];
        Osm[(r + 8) * 65 + cb + 1] = acc[nt8][3];
    }
    __syncthreads();

    // ---- coalesced epilogue: x1 = alpha*O/L + x ----
    {
        int q = t & 127, ch = (t >> 7) * 32;
        int n = q0 + q;
        float sc = __ldg(alpha) / Lq[q];
        const float* Ob = Osm + q * 65;
        float* x1 = g_x1 + b * 64 * NN;
        const float* xb = x + b * 64 * NN;
        #pragma unroll
        for (int c = 0; c < 32; c++) {
            int cc = ch + c;
            x1[cc * NN + n] = Ob[cc] * sc + xb[cc * NN + n];
        }
    }
}

// ---------------- K3: CAM gram partials (16 n-chunks) ----------------------
__global__ void __launch_bounds__(256) k3_gram()
{
    __shared__ float Xs[64 * 65];
    const int b = blockIdx.y, ch = blockIdx.x;
    const int t = threadIdx.x;
    const int cg = t >> 4, dg = t & 15;
    float acc[4][4];
    #pragma unroll
    for (int i = 0; i < 4; i++)
        #pragma unroll
        for (int j = 0; j < 4; j++) acc[i][j] = 0.f;

    const float* xb = g_x1 + b * 64 * NN + ch * 256;
    for (int sub = 0; sub < 4; sub++) {
        __syncthreads();
        #pragma unroll
        for (int rep = 0; rep < 16; rep++) {
            int idx = t + rep * 256;
            int c = idx >> 6, n = idx & 63;
            Xs[c * 65 + n] = xb[c * NN + sub * 64 + n];
        }
        __syncthreads();
        for (int n = 0; n < 64; n++) {
            float cv[4], dv[4];
            #pragma unroll
            for (int i = 0; i < 4; i++) cv[i] = Xs[(4 * cg + i) * 65 + n];
            #pragma unroll
            for (int j = 0; j < 4; j++) dv[j] = Xs[(4 * dg + j) * 65 + n];
            #pragma unroll
            for (int i = 0; i < 4; i++)
                #pragma unroll
                for (int j = 0; j < 4; j++) acc[i][j] += cv[i] * dv[j];
        }
    }
    float* dst = g_gramP + (b * 16 + ch) * 4096;
    #pragma unroll
    for (int i = 0; i < 4; i++)
        #pragma unroll
        for (int j = 0; j < 4; j++)
            dst[(4 * cg + i) * 64 + 4 * dg + j] = acc[i][j];
}

// ---------------- K3b: reduce partials + row softmax(-att) -----------------
__global__ void __launch_bounds__(256) k3b_soft()
{
    __shared__ float A[4096];
    const int b = blockIdx.x, t = threadIdx.x;
    const float* src = g_gramP + b * 16 * 4096;
    #pragma unroll
    for (int rep = 0; rep < 16; rep++) {
        int idx = t + rep * 256;
        float s = 0.f;
        #pragma unroll
        for (int ch = 0; ch < 16; ch++) s += src[ch * 4096 + idx];
        A[idx] = s;
    }
    __syncthreads();
    const int w = t >> 5, l = t & 31;
    float* dst = g_attG + b * 4096;
    for (int rr = 0; rr < 8; rr++) {
        int c = w * 8 + rr;
        float v0 = A[c * 64 + l], v1 = A[c * 64 + 32 + l];
        float mn = fminf(v0, v1);
        #pragma unroll
        for (int o = 16; o; o >>= 1) mn = fminf(mn, __shfl_xor_sync(0xffffffffu, mn, o));
        float e0 = __expf(mn - v0), e1 = __expf(mn - v1);
        float s = e0 + e1;
        #pragma unroll
        for (int o = 16; o; o >>= 1) s += __shfl_xor_sync(0xffffffffu, s, o);
        float inv = 1.f / s;
        dst[c * 64 + l]      = e0 * inv;
        dst[c * 64 + 32 + l] = e1 * inv;
    }
}

// ---------------- K4: fe = att @ x1 ; x2 = beta*fe + x1 --------------------
__global__ void __launch_bounds__(256) k4_cam(const float* __restrict__ beta)
{
    __shared__ __align__(16) float A[4096];
    const int b = blockIdx.y;
    const int t = threadIdx.x;
    const int n = blockIdx.x * 256 + t;
    const float* src = g_attG + b * 4096;
    #pragma unroll
    for (int rep = 0; rep < 16; rep++) A[t + rep * 256] = src[t + rep * 256];
    __syncthreads();
    float xr[64];
    const float* x1 = g_x1 + b * 64 * NN;
    #pragma unroll
    for (int d = 0; d < 64; d++) xr[d] = x1[d * NN + n];
    const float bt = __ldg(beta);
    float* x2 = g_x2 + b * 64 * NN;
    for (int c = 0; c < 64; c++) {
        float acc = 0.f;
        const float4* ar = (const float4*)(A + c * 64);
        #pragma unroll
        for (int d4 = 0; d4 < 16; d4++) {
            float4 a = ar[d4];
            acc += a.x * xr[4 * d4] + a.y * xr[4 * d4 + 1]
                 + a.z * xr[4 * d4 + 2] + a.w * xr[4 * d4 + 3];
        }
        x2[c * NN + n] = bt * acc + xr[c];
    }
}

// ---------------- K5: conv3x3 (bias skipped: cancels through BN) -----------
__global__ void __launch_bounds__(256) k5_conv(const float* __restrict__ cw)
{
    __shared__ __align__(16) float ins[16 * 324];  // [ic16][18][18]
    __shared__ ull ws2[16 * 16 * 9];               // [oc2(16)][ic(16)][9] oc-paired
    const int t = threadIdx.x;
    const int b = blockIdx.z;
    const int ocg = blockIdx.y;                    // oc base = ocg*32
    const int tile = blockIdx.x;
    const int th0 = (tile >> 2) * 16, tw0 = (tile & 3) * 16;
    const int og = t >> 6;                         // 0..3
    const int quad = t & 63;
    const int qr = quad >> 3, qc = quad & 7;
    const int r0 = 2 * qr, c0 = 2 * qc;

    const float* xb = g_x2 + b * 64 * NN;
    ull acc2[4][4];
    #pragma unroll
    for (int i = 0; i < 4; i++)
        #pragma unroll
        for (int j = 0; j < 4; j++) acc2[i][j] = 0ull;

    for (int cic = 0; cic < 4; cic++) {
        __syncthreads();
        for (int idx = t; idx < 16 * 324; idx += 256) {
            int ic = idx / 324, rem = idx % 324;
            int r = rem / 18, cc = rem % 18;
            int h = th0 + r - 1, w = tw0 + cc - 1;
            float v = 0.f;
            if ((unsigned)h < 64u && (unsigned)w < 64u)
                v = xb[(cic * 16 + ic) * NN + h * 64 + w];
            ins[idx] = v;
        }
        for (int idx = t; idx < 2304; idx += 256) {
            int oc2 = idx / 144, rem = idx % 144;
            int ic = rem / 9, kk = rem % 9;
            int oce = ocg * 32 + 2 * oc2;
            const float* wp = cw + (oce * 64 + cic * 16 + ic) * 9 + kk;
            ws2[idx] = pack2(wp[0], wp[64 * 9]);
        }
        __syncthreads();
        for (int ic = 0; ic < 16; ic++) {
            ull pvd[4][4];
            #pragma unroll
            for (int dr = 0; dr < 4; dr++)
                #pragma unroll
                for (int dc = 0; dc < 4; dc++) {
                    float v = ins[ic * 324 + (r0 + dr) * 18 + (c0 + dc)];
                    pvd[dr][dc] = pack2(v, v);
                }
            #pragma unroll
            for (int o2 = 0; o2 < 4; o2++) {
                const ull* wr = ws2 + ((og * 4 + o2) * 16 + ic) * 9;
                #pragma unroll
                for (int kh = 0; kh < 3; kh++)
                    #pragma unroll
                    for (int kw = 0; kw < 3; kw++) {
                        ull wv = wr[3 * kh + kw];
                        ffma2(acc2[o2][0], wv, pvd[kh][kw]);
                        ffma2(acc2[o2][1], wv, pvd[kh][kw + 1]);
                        ffma2(acc2[o2][2], wv, pvd[kh + 1][kw]);
                        ffma2(acc2[o2][3], wv, pvd[kh + 1][kw + 1]);
                    }
            }
        }
    }
    #pragma unroll
    for (int o2 = 0; o2 < 4; o2++) {
        int oce = ocg * 32 + (og * 4 + o2) * 2;
        #pragma unroll
        for (int pix = 0; pix < 4; pix++) {
            int ph = pix >> 1, pw = pix & 1;
            int h = th0 + r0 + ph, w = tw0 + c0 + pw;
            float lo, hi; unpack2(acc2[o2][pix], lo, hi);
            g_conv[(b * 128 + oce) * NN + h * 64 + w]       = lo;
            g_conv[(b * 128 + oce + 1) * NN + h * 64 + w]   = hi;
        }
    }
}

// ---------------- K6: BN batch stats per channel ---------------------------
__global__ void __launch_bounds__(256) k6_stats()
{
    __shared__ float rs[256], rs2[256];
    const int oc = blockIdx.x, t = threadIdx.x;
    float s = 0.f, s2 = 0.f;
    for (int idx = t; idx < 32768; idx += 256) {
        int bb = idx >> 12, n = idx & 4095;
        float v = g_conv[(bb * 128 + oc) * NN + n];
        s += v; s2 += v * v;
    }
    rs[t] = s; rs2[t] = s2;
    __syncthreads();
    for (int o = 128; o; o >>= 1) {
        if (t < o) { rs[t] += rs[t + o]; rs2[t] += rs2[t + o]; }
        __syncthreads();
    }
    if (t == 0) {
        float mean = rs[0] * (1.f / 32768.f);
        float var  = rs2[0] * (1.f / 32768.f) - mean * mean;
        g_mean[oc] = mean;
        g_rstd[oc] = rsqrtf(var + 1e-5f);
    }
}

// ---------------- K7: normalize + ReLU + maxpool(2,2,hpad) -----------------
__global__ void __launch_bounds__(256) k7_pool(const float* __restrict__ gamma,
                                              const float* __restrict__ bbeta,
                                              float* __restrict__ out)
{
    const int p = blockIdx.x;          // b*128 + oc
    const int oc = p & 127;
    const float a  = g_rstd[oc] * __ldg(gamma + oc);
    const float bc = __ldg(bbeta + oc) - g_mean[oc] * a;
    const float* cp = g_conv + p * NN;
    float* op = out + p * 33 * 32;
    for (int idx = threadIdx.x; idx < 1056; idx += 256) {
        int oh = idx >> 5, ow = idx & 31;
        int r0 = 2 * oh - 1, r1 = 2 * oh;
        int c0 = 2 * ow;
        float m = 0.f;  // ReLU floor; -inf pad rows excluded
        if (r0 >= 0) {
            m = fmaxf(m, cp[r0 * 64 + c0] * a + bc);
            m = fmaxf(m, cp[r0 * 64 + c0 + 1] * a + bc);
        }
        if (r1 < 64) {
            m = fmaxf(m, cp[r1 * 64 + c0] * a + bc);
            m = fmaxf(m, cp[r1 * 64 + c0 + 1] * a + bc);
        }
        op[idx] = m;
    }
}

extern "C" void kernel_launch(void* const* d_in, const int* in_sizes, int n_in,
                              void* d_out, int out_size)
{
    const float* x   = (const float*)d_in[0];
    const float* wb  = (const float*)d_in[1];
    const float* bb  = (const float*)d_in[2];
    const float* wc  = (const float*)d_in[3];
    const float* bc  = (const float*)d_in[4];
    const float* wd  = (const float*)d_in[5];
    const float* bd  = (const float*)d_in[6];
    const float* al  = (const float*)d_in[7];
    const float* be  = (const float*)d_in[8];
    const float* cw  = (const float*)d_in[9];
    const float* gam = (const float*)d_in[11];
    const float* bet = (const float*)d_in[12];
    float* out = (float*)d_out;

    k1_conv1x1<<<dim3(16, 8), 256>>>(x, wb, bb, wc, bc, wd, bd);
    k2_flash_mma<<<dim3(32, 8), 256>>>(x, al);
    k3_gram<<<dim3(16, 8), 256>>>();
    k3b_soft<<<8, 256>>>();
    k4_cam<<<dim3(16, 8), 256>>>(be);
    k5_conv<<<dim3(16, 4, 8), 256>>>(cw);
    k6_stats<<<128, 256>>>();
    k7_pool<<<1024, 256>>>(gam, bet, out);
}